// round 15
// baseline (speedup 1.0000x reference)
#include <cuda_runtime.h>
#include <cuda_bf16.h>

#define HW   4096
#define CCH  64
#define BB   4

// Scratch (allocation-free rule: __device__ globals)
__device__ float g_f[BB * HW * 8];            // [b][n][k]
__device__ float g_g[BB * HW * 8];            // [b][n][k]
__device__ float g_h[BB * CCH * HW];          // [b][c][n]
__device__ float g_part[BB * HW];             // denom sums
__device__ float g_rden[BB * HW];             // 1/denom
__device__ float g_O[BB * CCH * HW];          // attention output accumulator
__device__ __nv_bfloat16 g_vp[BB * CCH * HW]; // V' = h * rden, bf16 [b][c][n]

#define LDSM4(r0, r1, r2, r3, addr) \
    asm volatile("ldmatrix.sync.aligned.m8n8.x4.shared.b16 {%0,%1,%2,%3}, [%4];" \
                 : "=r"(r0), "=r"(r1), "=r"(r2), "=r"(r3) : "r"(addr))

#define MMA16816(d, a, b0, b1) \
    asm volatile("mma.sync.aligned.m16n8k16.row.col.f32.bf16.bf16.f32 " \
                 "{%0,%1,%2,%3}, {%4,%5,%6,%7}, {%8,%9}, {%0,%1,%2,%3};" \
                 : "+f"((d)[0]), "+f"((d)[1]), "+f"((d)[2]), "+f"((d)[3]) \
                 : "r"((a)[0]), "r"((a)[1]), "r"((a)[2]), "r"((a)[3]), \
                   "r"(b0), "r"(b1))

__device__ __forceinline__ unsigned pk(float hi, float lo) {
    unsigned r;
    asm("cvt.rn.bf16x2.f32 %0, %1, %2;" : "=r"(r) : "f"(hi), "f"(lo));
    return r;
}

// split helper: store [hi pair][lo pair] as bf162
__device__ __forceinline__ void split2(float a, float b,
                                       __nv_bfloat162* hi, __nv_bfloat162* lo) {
    __nv_bfloat16 ha = __float2bfloat16(a), hb = __float2bfloat16(b);
    __nv_bfloat162 h; h.x = ha; h.y = hb;
    __nv_bfloat162 l;
    l.x = __float2bfloat16(a - __bfloat162float(ha));
    l.y = __float2bfloat16(b - __bfloat162float(hb));
    *hi = h; *lo = l;
}

// ---------------------------------------------------------------------------
__global__ __launch_bounds__(256) void kZ()
{
    ((float4*)g_O)[blockIdx.x * 256 + threadIdx.x] = make_float4(0.f, 0.f, 0.f, 0.f);
}
__global__ __launch_bounds__(256) void kZ2()
{
    ((float4*)g_part)[blockIdx.x * 256 + threadIdx.x] = make_float4(0.f, 0.f, 0.f, 0.f);
}

// ---------------------------------------------------------------------------
// Kernel A: f = Wf@x+bf, g = Wg@x+bg, h = Wh@x+bh (1x1 convs)  [unchanged]
// ---------------------------------------------------------------------------
__global__ __launch_bounds__(256) void kA(
    const float* __restrict__ x,
    const float* __restrict__ Wf, const float* __restrict__ bf,
    const float* __restrict__ Wg, const float* __restrict__ bg,
    const float* __restrict__ Wh, const float* __restrict__ bh)
{
    __shared__ float xs[64 * 128];
    const int t  = threadIdx.x;
    const int b  = blockIdx.y;
    const int n0 = blockIdx.x * 128;

    #pragma unroll
    for (int r = 0; r < 32; r++) {
        int lin = r * 256 + t;
        int c = lin >> 7, nn = lin & 127;
        xs[lin] = x[((b * 64 + c) << 12) + n0 + nn];
    }
    __syncthreads();

    const int n = t & 127, half = t >> 7;
    const int rowbase = half * 32;
    const float* Wfg = half ? Wg : Wf;
    const float* bfg = half ? bg : bf;

    float acch[32], accfg[8];
    #pragma unroll
    for (int o = 0; o < 32; o++) acch[o] = bh[rowbase + o];
    #pragma unroll
    for (int k = 0; k < 8; k++)  accfg[k] = bfg[k];

    #pragma unroll
    for (int c0 = 0; c0 < 64; c0 += 8) {
        float xv[8];
        #pragma unroll
        for (int j = 0; j < 8; j++) xv[j] = xs[(c0 + j) * 128 + n];

        #pragma unroll
        for (int o = 0; o < 32; o++) {
            const float4* w = (const float4*)(Wh + (rowbase + o) * 64 + c0);
            float4 w0 = w[0], w1 = w[1];
            acch[o] += w0.x * xv[0] + w0.y * xv[1] + w0.z * xv[2] + w0.w * xv[3]
                     + w1.x * xv[4] + w1.y * xv[5] + w1.z * xv[6] + w1.w * xv[7];
        }
        #pragma unroll
        for (int k = 0; k < 8; k++) {
            const float4* w = (const float4*)(Wfg + k * 64 + c0);
            float4 w0 = w[0], w1 = w[1];
            accfg[k] += w0.x * xv[0] + w0.y * xv[1] + w0.z * xv[2] + w0.w * xv[3]
                      + w1.x * xv[4] + w1.y * xv[5] + w1.z * xv[6] + w1.w * xv[7];
        }
    }

    const int ng = n0 + n;
    #pragma unroll
    for (int o = 0; o < 32; o++)
        g_h[((b * 64 + rowbase + o) << 12) + ng] = acch[o];

    float* dst = (half ? g_g : g_f) + (b * HW + ng) * 8;
    *(float4*)(dst)     = make_float4(accfg[0], accfg[1], accfg[2], accfg[3]);
    *(float4*)(dst + 4) = make_float4(accfg[4], accfg[5], accfg[6], accfg[7]);
}

// ---------------------------------------------------------------------------
// Kernel B1 (mma version): denom[b][n] = sum_m exp(f_m . g_n)
// Block = (n-chunk of 64, b); 256 thr, 8 warps (4 n16-groups x 2 m64-halves).
// Loops 32 m-chunks of 128; S' = G(n16,k16-split) @ F^T via mma; exp; reduce.
// ---------------------------------------------------------------------------
__global__ __launch_bounds__(256) void kB1()
{
    __shared__ __align__(16) __nv_bfloat16 gsb[64 * 24];
    __shared__ __align__(16) __nv_bfloat16 fsb[128 * 24];

    const int tid = threadIdx.x, wid = tid >> 5, lane = tid & 31;
    const int b = blockIdx.y;
    const int n_base = blockIdx.x * 64;

    // stage g (hi|lo), 2 values per thread
    {
        int n = tid >> 2, k2 = (tid & 3) * 2;
        float2 v = *(const float2*)&g_g[(b * HW + n_base + n) * 8 + k2];
        __nv_bfloat162 hi, lo;
        split2(v.x, v.y, &hi, &lo);
        *(__nv_bfloat162*)&gsb[n * 24 + k2]     = hi;
        *(__nv_bfloat162*)&gsb[n * 24 + 8 + k2] = lo;
    }
    __syncthreads();

    const unsigned gsS = (unsigned)__cvta_generic_to_shared(gsb);
    const unsigned fsS = (unsigned)__cvta_generic_to_shared(fsb);

    const int wn16 = (wid & 3) * 16;
    const int wmh  = (wid >> 2) * 64;
    const int grp = lane >> 3;
    const int grow = (grp >> 1) * 8 + (lane & 7);
    const int gcol = (grp & 1) * 8;

    // A frag: g [hi|lo] m16k16
    unsigned ga[4];
    {
        unsigned addr = gsS + (((wn16 + (lane & 15)) * 24 + (lane >> 4) * 8) << 1);
        LDSM4(ga[0], ga[1], ga[2], ga[3], addr);
    }

    float dsum0 = 0.f, dsum1 = 0.f;

    for (int mc = 0; mc < 32; mc++) {
        __syncthreads();
        {
            int m = tid >> 1, k4 = (tid & 1) * 4;
            float4 v = *(const float4*)&g_f[(b * HW + mc * 128 + m) * 8 + k4];
            __nv_bfloat162 hi0, lo0, hi1, lo1;
            split2(v.x, v.y, &hi0, &lo0);
            split2(v.z, v.w, &hi1, &lo1);
            *(__nv_bfloat162*)&fsb[m * 24 + k4]         = hi0;
            *(__nv_bfloat162*)&fsb[m * 24 + k4 + 2]     = hi1;
            *(__nv_bfloat162*)&fsb[m * 24 + 8 + k4]     = lo0;
            *(__nv_bfloat162*)&fsb[m * 24 + 8 + k4 + 2] = lo1;
        }
        __syncthreads();

        #pragma unroll
        for (int mg = 0; mg < 4; mg++) {
            unsigned fb[4];
            unsigned addr = fsS + (((wmh + mg * 16 + grow) * 24 + gcol) << 1);
            LDSM4(fb[0], fb[1], fb[2], fb[3], addr);

            float a0[4] = {0.f, 0.f, 0.f, 0.f};
            float a1[4] = {0.f, 0.f, 0.f, 0.f};
            MMA16816(a0, ga, fb[0], fb[0]);   // g . f_hi   (m 0-7)
            MMA16816(a0, ga, fb[1], fb[1]);   // g . f_lo
            MMA16816(a1, ga, fb[2], fb[2]);   // m 8-15
            MMA16816(a1, ga, fb[3], fb[3]);

            dsum0 += __expf(a0[0]) + __expf(a0[1]) + __expf(a1[0]) + __expf(a1[1]);
            dsum1 += __expf(a0[2]) + __expf(a0[3]) + __expf(a1[2]) + __expf(a1[3]);
        }
    }

    dsum0 += __shfl_xor_sync(0xffffffffu, dsum0, 1);
    dsum0 += __shfl_xor_sync(0xffffffffu, dsum0, 2);
    dsum1 += __shfl_xor_sync(0xffffffffu, dsum1, 1);
    dsum1 += __shfl_xor_sync(0xffffffffu, dsum1, 2);
    if ((lane & 3) == 0) {
        int n = n_base + wn16 + (lane >> 2);
        atomicAdd(&g_part[b * HW + n],     dsum0);
        atomicAdd(&g_part[b * HW + n + 8], dsum1);
    }
}

__global__ __launch_bounds__(256) void kB2()
{
    int i = blockIdx.x * 256 + threadIdx.x;      // 16384 total
    g_rden[i] = 1.0f / g_part[i];
}

// ---------------------------------------------------------------------------
// Kernel V: g_vp[b][c][n] = bf16( h * rden )
// ---------------------------------------------------------------------------
__global__ __launch_bounds__(256) void kV()
{
    int idx = blockIdx.x * 256 + threadIdx.x;    // 0..262143, 4 n each
    int b = idx >> 16;
    int rem = idx & 65535;
    int c = rem >> 10;
    int n = (rem & 1023) * 4;
    float4 h = *(const float4*)&g_h[((b * 64 + c) << 12) + n];
    float4 r = *(const float4*)&g_rden[b * HW + n];
    __nv_bfloat162 p0, p1;
    p0.x = __float2bfloat16(h.x * r.x); p0.y = __float2bfloat16(h.y * r.y);
    p1.x = __float2bfloat16(h.z * r.z); p1.y = __float2bfloat16(h.w * r.w);
    __nv_bfloat16* dst = &g_vp[((b * 64 + c) << 12) + n];
    *(__nv_bfloat162*)(dst)     = p0;
    *(__nv_bfloat162*)(dst + 2) = p1;
}

// ---------------------------------------------------------------------------
// Kernel C: masked attention GEMM, fully tensor-core, register-resident P.
// Block tile 128m x 64natt x 64c; 8 warps, warp = m16 x (natt,k)=64.
// S via split-bf16 mma (exact); exp+mask on fragments; pack in regs; O-mma.
// Tasks: (b, mt of 128 m-rows, chunk of 16 n-tiles) -> 320 blocks.
// ---------------------------------------------------------------------------
__global__ __launch_bounds__(256) void kC()
{
    __shared__ __align__(16) __nv_bfloat16 fsb[128 * 24];
    __shared__ __align__(16) __nv_bfloat16 gsb[64 * 24];
    __shared__ __align__(16) __nv_bfloat16 Vt[64 * 72];

    const int tid = threadIdx.x, wid = tid >> 5, lane = tid & 31;
    const int bid = blockIdx.x;
    const int b = bid & 3;
    int t = bid >> 2;

    int mt = 0;
    for (;;) {
        int ch = (64 - 2 * mt + 15) >> 4;
        if (t < ch) break;
        t -= ch; mt++;
    }
    const int m_base = mt * 128;
    const int nt_begin = 2 * mt + t * 16;
    const int nt_end = (nt_begin + 16 < 64) ? nt_begin + 16 : 64;

    // stage f (hi|lo) once: 128 rows
    {
        int m = tid >> 1, k4 = (tid & 1) * 4;
        float4 v = *(const float4*)&g_f[(b * HW + m_base + m) * 8 + k4];
        __nv_bfloat162 hi0, lo0, hi1, lo1;
        split2(v.x, v.y, &hi0, &lo0);
        split2(v.z, v.w, &hi1, &lo1);
        *(__nv_bfloat162*)&fsb[m * 24 + k4]         = hi0;
        *(__nv_bfloat162*)&fsb[m * 24 + k4 + 2]     = hi1;
        *(__nv_bfloat162*)&fsb[m * 24 + 8 + k4]     = lo0;
        *(__nv_bfloat162*)&fsb[m * 24 + 8 + k4 + 2] = lo1;
    }
    __syncthreads();

    const unsigned fsS = (unsigned)__cvta_generic_to_shared(fsb);
    const unsigned gsS = (unsigned)__cvta_generic_to_shared(gsb);
    const unsigned vtS = (unsigned)__cvta_generic_to_shared(Vt);

    const int wm16 = wid * 16;
    const int grp = lane >> 3;
    const int grow = (grp >> 1) * 8 + (lane & 7);
    const int gcol = (grp & 1) * 8;
    const int mloc = wm16 + (lane >> 2);
    const int nbase = 2 * (lane & 3);

    // A frag: f [hi|lo] m16k16, once
    unsigned fa[4];
    {
        unsigned addr = fsS + (((wm16 + (lane & 15)) * 24 + (lane >> 4) * 8) << 1);
        LDSM4(fa[0], fa[1], fa[2], fa[3], addr);
    }

    float accO[8][4];
    #pragma unroll
    for (int i = 0; i < 8; i++)
        #pragma unroll
        for (int j = 0; j < 4; j++) accO[i][j] = 0.f;

    for (int nt = nt_begin; nt < nt_end; nt++) {
        const int n0 = nt * 64;

        __syncthreads();
        // stage g (hi|lo)
        {
            int n = tid >> 2, k2 = (tid & 3) * 2;
            float2 v = *(const float2*)&g_g[(b * HW + n0 + n) * 8 + k2];
            __nv_bfloat162 hi, lo;
            split2(v.x, v.y, &hi, &lo);
            *(__nv_bfloat162*)&gsb[n * 24 + k2]     = hi;
            *(__nv_bfloat162*)&gsb[n * 24 + 8 + k2] = lo;
        }
        // stage V' tile (bf16 copy), rows=c, cols=natt
        #pragma unroll
        for (int r = 0; r < 2; r++) {
            int lin = r * 256 + tid;
            int c = lin >> 3, s8 = (lin & 7) * 8;
            *(uint4*)&Vt[c * 72 + s8] =
                *(const uint4*)&g_vp[((b * 64 + c) << 12) + n0 + s8];
        }
        __syncthreads();

        // G B-frags: 4 n16-groups
        unsigned gb[4][4];
        #pragma unroll
        for (int q = 0; q < 4; q++) {
            unsigned addr = gsS + (((q * 16 + grow) * 24 + gcol) << 1);
            LDSM4(gb[q][0], gb[q][1], gb[q][2], gb[q][3], addr);
        }

        // S = f . g  (split-bf16, exact): acc m16 x n64
        float s[8][4];
        #pragma unroll
        for (int i = 0; i < 8; i++)
            #pragma unroll
            for (int j = 0; j < 4; j++) s[i][j] = 0.f;
        #pragma unroll
        for (int ng = 0; ng < 8; ng++) {
            const int q = ng >> 1, rr = (ng & 1) * 2;
            MMA16816(s[ng], fa, gb[q][rr],     gb[q][rr]);      // f . g_hi
            MMA16816(s[ng], fa, gb[q][rr + 1], gb[q][rr + 1]);  // f . g_lo
        }

        // exp + causal-ish mask (n_glob >= m_glob)
        const int off = n0 - m_base;
        if (off < 128) {
            #pragma unroll
            for (int ng = 0; ng < 8; ng++) {
                int d = off + ng * 8 + nbase - mloc;
                s[ng][0] = (d     >= 0) ? __expf(s[ng][0]) : 0.f;
                s[ng][1] = (d + 1 >= 0) ? __expf(s[ng][1]) : 0.f;
                s[ng][2] = (d - 8 >= 0) ? __expf(s[ng][2]) : 0.f;
                s[ng][3] = (d - 7 >= 0) ? __expf(s[ng][3]) : 0.f;
            }
        } else {
            #pragma unroll
            for (int ng = 0; ng < 8; ng++) {
                s[ng][0] = __expf(s[ng][0]);
                s[ng][1] = __expf(s[ng][1]);
                s[ng][2] = __expf(s[ng][2]);
                s[ng][3] = __expf(s[ng][3]);
            }
        }

        // pack P fragments (registers): 4 k16 A-frags
        unsigned pa[4][4];
        #pragma unroll
        for (int j = 0; j < 4; j++) {
            pa[j][0] = pk(s[2 * j][1],     s[2 * j][0]);
            pa[j][1] = pk(s[2 * j][3],     s[2 * j][2]);
            pa[j][2] = pk(s[2 * j + 1][1], s[2 * j + 1][0]);
            pa[j][3] = pk(s[2 * j + 1][3], s[2 * j + 1][2]);
        }

        // O += P @ V'
        #pragma unroll
        for (int j = 0; j < 4; j++) {
            const int kb = j * 16;
            unsigned vb[4][4];
            #pragma unroll
            for (int q2 = 0; q2 < 4; q2++) {
                unsigned addr = vtS + (((q2 * 16 + grow) * 72 + kb + gcol) << 1);
                LDSM4(vb[q2][0], vb[q2][1], vb[q2][2], vb[q2][3], addr);
            }
            #pragma unroll
            for (int cg = 0; cg < 8; cg++) {
                const int q2 = cg >> 1, rr = (cg & 1) * 2;
                MMA16816(accO[cg], pa[j], vb[q2][rr], vb[q2][rr + 1]);
            }
        }
    }

    // epilogue: atomic accumulate into g_O[b][c][m]
    const int m0g = m_base + wm16 + (lane >> 2);
    #pragma unroll
    for (int cg = 0; cg < 8; cg++) {
        int c = cg * 8 + nbase;
        atomicAdd(&g_O[((b * 64 + c    ) << 12) + m0g],     accO[cg][0]);
        atomicAdd(&g_O[((b * 64 + c + 1) << 12) + m0g],     accO[cg][1]);
        atomicAdd(&g_O[((b * 64 + c    ) << 12) + m0g + 8], accO[cg][2]);
        atomicAdd(&g_O[((b * 64 + c + 1) << 12) + m0g + 8], accO[cg][3]);
    }
}

// ---------------------------------------------------------------------------
__global__ __launch_bounds__(256) void kE(
    const float* __restrict__ x,
    const float* __restrict__ gamma,
    float* __restrict__ out)
{
    const float gm = gamma[0];
    int i = blockIdx.x * 256 + threadIdx.x;
    float4 o  = ((const float4*)g_O)[i];
    float4 xv = ((const float4*)x)[i];
    ((float4*)out)[i] = make_float4(gm * o.x + xv.x, gm * o.y + xv.y,
                                    gm * o.z + xv.z, gm * o.w + xv.w);
}

// ---------------------------------------------------------------------------
extern "C" void kernel_launch(void* const* d_in, const int* in_sizes, int n_in,
                              void* d_out, int out_size)
{
    const float* x     = (const float*)d_in[0];
    const float* Wf    = (const float*)d_in[1];
    const float* bf    = (const float*)d_in[2];
    const float* Wg    = (const float*)d_in[3];
    const float* bg    = (const float*)d_in[4];
    const float* Wh    = (const float*)d_in[5];
    const float* bh    = (const float*)d_in[6];
    const float* gamma = (const float*)d_in[7];
    float* out = (float*)d_out;

    kZ<<<1024, 256>>>();
    kZ2<<<16, 256>>>();
    kA<<<dim3(32, 4), 256>>>(x, Wf, bf, Wg, bg, Wh, bh);
    kB1<<<dim3(64, 4), 256>>>();
    kB2<<<64, 256>>>();
    kV<<<1024, 256>>>();
    kC<<<320, 256>>>();
    kE<<<1024, 256>>>(x, gamma, out);
}

// round 16
// speedup vs baseline: 1.0136x; 1.0136x over previous
#include <cuda_runtime.h>
#include <cuda_bf16.h>

#define HW   4096
#define CCH  64
#define BB   4

// Scratch (allocation-free rule: __device__ globals)
__device__ float g_f[BB * HW * 8];            // [b][n][k]
__device__ float g_g[BB * HW * 8];            // [b][n][k]
__device__ float g_h[BB * CCH * HW];          // [b][c][n]
__device__ float g_part[BB * HW];             // denom sums
__device__ float g_rden[BB * HW];             // 1/denom
__device__ float g_O[BB * CCH * HW];          // attention output accumulator
__device__ __nv_bfloat16 g_vp[BB * CCH * HW]; // V' = h * rden, bf16 [b][c][n]

#define LDSM4(r0, r1, r2, r3, addr) \
    asm volatile("ldmatrix.sync.aligned.m8n8.x4.shared.b16 {%0,%1,%2,%3}, [%4];" \
                 : "=r"(r0), "=r"(r1), "=r"(r2), "=r"(r3) : "r"(addr))

#define MMA16816(d, a, b0, b1) \
    asm volatile("mma.sync.aligned.m16n8k16.row.col.f32.bf16.bf16.f32 " \
                 "{%0,%1,%2,%3}, {%4,%5,%6,%7}, {%8,%9}, {%0,%1,%2,%3};" \
                 : "+f"((d)[0]), "+f"((d)[1]), "+f"((d)[2]), "+f"((d)[3]) \
                 : "r"((a)[0]), "r"((a)[1]), "r"((a)[2]), "r"((a)[3]), \
                   "r"(b0), "r"(b1))

__device__ __forceinline__ unsigned pk(float hi, float lo) {
    unsigned r;
    asm("cvt.rn.bf16x2.f32 %0, %1, %2;" : "=r"(r) : "f"(hi), "f"(lo));
    return r;
}

// split helper: store [hi pair][lo pair] as bf162
__device__ __forceinline__ void split2(float a, float b,
                                       __nv_bfloat162* hi, __nv_bfloat162* lo) {
    __nv_bfloat16 ha = __float2bfloat16(a), hb = __float2bfloat16(b);
    __nv_bfloat162 h; h.x = ha; h.y = hb;
    __nv_bfloat162 l;
    l.x = __float2bfloat16(a - __bfloat162float(ha));
    l.y = __float2bfloat16(b - __bfloat162float(hb));
    *hi = h; *lo = l;
}

// ---------------------------------------------------------------------------
__global__ __launch_bounds__(256) void kZ()
{
    ((float4*)g_O)[blockIdx.x * 256 + threadIdx.x] = make_float4(0.f, 0.f, 0.f, 0.f);
}
__global__ __launch_bounds__(256) void kZ2()
{
    ((float4*)g_part)[blockIdx.x * 256 + threadIdx.x] = make_float4(0.f, 0.f, 0.f, 0.f);
}

// ---------------------------------------------------------------------------
// Kernel A: f = Wf@x+bf, g = Wg@x+bg, h = Wh@x+bh (1x1 convs)  [unchanged]
// ---------------------------------------------------------------------------
__global__ __launch_bounds__(256) void kA(
    const float* __restrict__ x,
    const float* __restrict__ Wf, const float* __restrict__ bf,
    const float* __restrict__ Wg, const float* __restrict__ bg,
    const float* __restrict__ Wh, const float* __restrict__ bh)
{
    __shared__ float xs[64 * 128];
    const int t  = threadIdx.x;
    const int b  = blockIdx.y;
    const int n0 = blockIdx.x * 128;

    #pragma unroll
    for (int r = 0; r < 32; r++) {
        int lin = r * 256 + t;
        int c = lin >> 7, nn = lin & 127;
        xs[lin] = x[((b * 64 + c) << 12) + n0 + nn];
    }
    __syncthreads();

    const int n = t & 127, half = t >> 7;
    const int rowbase = half * 32;
    const float* Wfg = half ? Wg : Wf;
    const float* bfg = half ? bg : bf;

    float acch[32], accfg[8];
    #pragma unroll
    for (int o = 0; o < 32; o++) acch[o] = bh[rowbase + o];
    #pragma unroll
    for (int k = 0; k < 8; k++)  accfg[k] = bfg[k];

    #pragma unroll
    for (int c0 = 0; c0 < 64; c0 += 8) {
        float xv[8];
        #pragma unroll
        for (int j = 0; j < 8; j++) xv[j] = xs[(c0 + j) * 128 + n];

        #pragma unroll
        for (int o = 0; o < 32; o++) {
            const float4* w = (const float4*)(Wh + (rowbase + o) * 64 + c0);
            float4 w0 = w[0], w1 = w[1];
            acch[o] += w0.x * xv[0] + w0.y * xv[1] + w0.z * xv[2] + w0.w * xv[3]
                     + w1.x * xv[4] + w1.y * xv[5] + w1.z * xv[6] + w1.w * xv[7];
        }
        #pragma unroll
        for (int k = 0; k < 8; k++) {
            const float4* w = (const float4*)(Wfg + k * 64 + c0);
            float4 w0 = w[0], w1 = w[1];
            accfg[k] += w0.x * xv[0] + w0.y * xv[1] + w0.z * xv[2] + w0.w * xv[3]
                      + w1.x * xv[4] + w1.y * xv[5] + w1.z * xv[6] + w1.w * xv[7];
        }
    }

    const int ng = n0 + n;
    #pragma unroll
    for (int o = 0; o < 32; o++)
        g_h[((b * 64 + rowbase + o) << 12) + ng] = acch[o];

    float* dst = (half ? g_g : g_f) + (b * HW + ng) * 8;
    *(float4*)(dst)     = make_float4(accfg[0], accfg[1], accfg[2], accfg[3]);
    *(float4*)(dst + 4) = make_float4(accfg[4], accfg[5], accfg[6], accfg[7]);
}

// ---------------------------------------------------------------------------
// Kernel B1 (mma version): denom[b][n] = sum_m exp(f_m . g_n)
// Block = (n-chunk of 64, b); 256 thr, 8 warps (4 n16-groups x 2 m64-halves).
// Loops 32 m-chunks of 128; S' = G(n16,k16-split) @ F^T via mma; exp; reduce.
// ---------------------------------------------------------------------------
__global__ __launch_bounds__(256) void kB1()
{
    __shared__ __align__(16) __nv_bfloat16 gsb[64 * 24];
    __shared__ __align__(16) __nv_bfloat16 fsb[128 * 24];

    const int tid = threadIdx.x, wid = tid >> 5, lane = tid & 31;
    const int b = blockIdx.y;
    const int n_base = blockIdx.x * 64;

    // stage g (hi|lo), 2 values per thread
    {
        int n = tid >> 2, k2 = (tid & 3) * 2;
        float2 v = *(const float2*)&g_g[(b * HW + n_base + n) * 8 + k2];
        __nv_bfloat162 hi, lo;
        split2(v.x, v.y, &hi, &lo);
        *(__nv_bfloat162*)&gsb[n * 24 + k2]     = hi;
        *(__nv_bfloat162*)&gsb[n * 24 + 8 + k2] = lo;
    }
    __syncthreads();

    const unsigned gsS = (unsigned)__cvta_generic_to_shared(gsb);
    const unsigned fsS = (unsigned)__cvta_generic_to_shared(fsb);

    const int wn16 = (wid & 3) * 16;
    const int wmh  = (wid >> 2) * 64;
    const int grp = lane >> 3;
    const int grow = (grp >> 1) * 8 + (lane & 7);
    const int gcol = (grp & 1) * 8;

    // A frag: g [hi|lo] m16k16
    unsigned ga[4];
    {
        unsigned addr = gsS + (((wn16 + (lane & 15)) * 24 + (lane >> 4) * 8) << 1);
        LDSM4(ga[0], ga[1], ga[2], ga[3], addr);
    }

    float dsum0 = 0.f, dsum1 = 0.f;

    for (int mc = 0; mc < 32; mc++) {
        __syncthreads();
        {
            int m = tid >> 1, k4 = (tid & 1) * 4;
            float4 v = *(const float4*)&g_f[(b * HW + mc * 128 + m) * 8 + k4];
            __nv_bfloat162 hi0, lo0, hi1, lo1;
            split2(v.x, v.y, &hi0, &lo0);
            split2(v.z, v.w, &hi1, &lo1);
            *(__nv_bfloat162*)&fsb[m * 24 + k4]         = hi0;
            *(__nv_bfloat162*)&fsb[m * 24 + k4 + 2]     = hi1;
            *(__nv_bfloat162*)&fsb[m * 24 + 8 + k4]     = lo0;
            *(__nv_bfloat162*)&fsb[m * 24 + 8 + k4 + 2] = lo1;
        }
        __syncthreads();

        #pragma unroll
        for (int mg = 0; mg < 4; mg++) {
            unsigned fb[4];
            unsigned addr = fsS + (((wmh + mg * 16 + grow) * 24 + gcol) << 1);
            LDSM4(fb[0], fb[1], fb[2], fb[3], addr);

            float a0[4] = {0.f, 0.f, 0.f, 0.f};
            float a1[4] = {0.f, 0.f, 0.f, 0.f};
            MMA16816(a0, ga, fb[0], fb[0]);   // g . f_hi   (m 0-7)
            MMA16816(a0, ga, fb[1], fb[1]);   // g . f_lo
            MMA16816(a1, ga, fb[2], fb[2]);   // m 8-15
            MMA16816(a1, ga, fb[3], fb[3]);

            dsum0 += __expf(a0[0]) + __expf(a0[1]) + __expf(a1[0]) + __expf(a1[1]);
            dsum1 += __expf(a0[2]) + __expf(a0[3]) + __expf(a1[2]) + __expf(a1[3]);
        }
    }

    dsum0 += __shfl_xor_sync(0xffffffffu, dsum0, 1);
    dsum0 += __shfl_xor_sync(0xffffffffu, dsum0, 2);
    dsum1 += __shfl_xor_sync(0xffffffffu, dsum1, 1);
    dsum1 += __shfl_xor_sync(0xffffffffu, dsum1, 2);
    if ((lane & 3) == 0) {
        int n = n_base + wn16 + (lane >> 2);
        atomicAdd(&g_part[b * HW + n],     dsum0);
        atomicAdd(&g_part[b * HW + n + 8], dsum1);
    }
}

__global__ __launch_bounds__(256) void kB2()
{
    int i = blockIdx.x * 256 + threadIdx.x;      // 16384 total
    g_rden[i] = 1.0f / g_part[i];
}

// ---------------------------------------------------------------------------
// Kernel V: g_vp[b][c][n] = bf16( h * rden )
// ---------------------------------------------------------------------------
__global__ __launch_bounds__(256) void kV()
{
    int idx = blockIdx.x * 256 + threadIdx.x;    // 0..262143, 4 n each
    int b = idx >> 16;
    int rem = idx & 65535;
    int c = rem >> 10;
    int n = (rem & 1023) * 4;
    float4 h = *(const float4*)&g_h[((b * 64 + c) << 12) + n];
    float4 r = *(const float4*)&g_rden[b * HW + n];
    __nv_bfloat162 p0, p1;
    p0.x = __float2bfloat16(h.x * r.x); p0.y = __float2bfloat16(h.y * r.y);
    p1.x = __float2bfloat16(h.z * r.z); p1.y = __float2bfloat16(h.w * r.w);
    __nv_bfloat16* dst = &g_vp[((b * 64 + c) << 12) + n];
    *(__nv_bfloat162*)(dst)     = p0;
    *(__nv_bfloat162*)(dst + 2) = p1;
}

// ---------------------------------------------------------------------------
// Kernel C: masked attention GEMM, fully tensor-core, register-resident P.
// Block tile 128m x 64natt x 64c; 8 warps, warp = m16 x (natt,k)=64.
// S via split-bf16 mma (exact); exp+mask on fragments; pack in regs; O-mma.
// Tasks: (b, mt of 128 m-rows, chunk of 16 n-tiles) -> 320 blocks.
// ---------------------------------------------------------------------------
__global__ __launch_bounds__(256) void kC()
{
    __shared__ __align__(16) __nv_bfloat16 fsb[128 * 24];
    __shared__ __align__(16) __nv_bfloat16 gsb[64 * 24];
    __shared__ __align__(16) __nv_bfloat16 Vt[64 * 72];

    const int tid = threadIdx.x, wid = tid >> 5, lane = tid & 31;
    const int bid = blockIdx.x;
    const int b = bid & 3;
    int t = bid >> 2;

    int mt = 0;
    for (;;) {
        int ch = (64 - 2 * mt + 15) >> 4;
        if (t < ch) break;
        t -= ch; mt++;
    }
    const int m_base = mt * 128;
    const int nt_begin = 2 * mt + t * 16;
    const int nt_end = (nt_begin + 16 < 64) ? nt_begin + 16 : 64;

    // stage f (hi|lo) once: 128 rows
    {
        int m = tid >> 1, k4 = (tid & 1) * 4;
        float4 v = *(const float4*)&g_f[(b * HW + m_base + m) * 8 + k4];
        __nv_bfloat162 hi0, lo0, hi1, lo1;
        split2(v.x, v.y, &hi0, &lo0);
        split2(v.z, v.w, &hi1, &lo1);
        *(__nv_bfloat162*)&fsb[m * 24 + k4]         = hi0;
        *(__nv_bfloat162*)&fsb[m * 24 + k4 + 2]     = hi1;
        *(__nv_bfloat162*)&fsb[m * 24 + 8 + k4]     = lo0;
        *(__nv_bfloat162*)&fsb[m * 24 + 8 + k4 + 2] = lo1;
    }
    __syncthreads();

    const unsigned fsS = (unsigned)__cvta_generic_to_shared(fsb);
    const unsigned gsS = (unsigned)__cvta_generic_to_shared(gsb);
    const unsigned vtS = (unsigned)__cvta_generic_to_shared(Vt);

    const int wm16 = wid * 16;
    const int grp = lane >> 3;
    const int grow = (grp >> 1) * 8 + (lane & 7);
    const int gcol = (grp & 1) * 8;
    const int mloc = wm16 + (lane >> 2);
    const int nbase = 2 * (lane & 3);

    // A frag: f [hi|lo] m16k16, once
    unsigned fa[4];
    {
        unsigned addr = fsS + (((wm16 + (lane & 15)) * 24 + (lane >> 4) * 8) << 1);
        LDSM4(fa[0], fa[1], fa[2], fa[3], addr);
    }

    float accO[8][4];
    #pragma unroll
    for (int i = 0; i < 8; i++)
        #pragma unroll
        for (int j = 0; j < 4; j++) accO[i][j] = 0.f;

    for (int nt = nt_begin; nt < nt_end; nt++) {
        const int n0 = nt * 64;

        __syncthreads();
        // stage g (hi|lo)
        {
            int n = tid >> 2, k2 = (tid & 3) * 2;
            float2 v = *(const float2*)&g_g[(b * HW + n0 + n) * 8 + k2];
            __nv_bfloat162 hi, lo;
            split2(v.x, v.y, &hi, &lo);
            *(__nv_bfloat162*)&gsb[n * 24 + k2]     = hi;
            *(__nv_bfloat162*)&gsb[n * 24 + 8 + k2] = lo;
        }
        // stage V' tile (bf16 copy), rows=c, cols=natt
        #pragma unroll
        for (int r = 0; r < 2; r++) {
            int lin = r * 256 + tid;
            int c = lin >> 3, s8 = (lin & 7) * 8;
            *(uint4*)&Vt[c * 72 + s8] =
                *(const uint4*)&g_vp[((b * 64 + c) << 12) + n0 + s8];
        }
        __syncthreads();

        // G B-frags: 4 n16-groups
        unsigned gb[4][4];
        #pragma unroll
        for (int q = 0; q < 4; q++) {
            unsigned addr = gsS + (((q * 16 + grow) * 24 + gcol) << 1);
            LDSM4(gb[q][0], gb[q][1], gb[q][2], gb[q][3], addr);
        }

        // S = f . g  (split-bf16, exact): acc m16 x n64
        float s[8][4];
        #pragma unroll
        for (int i = 0; i < 8; i++)
            #pragma unroll
            for (int j = 0; j < 4; j++) s[i][j] = 0.f;
        #pragma unroll
        for (int ng = 0; ng < 8; ng++) {
            const int q = ng >> 1, rr = (ng & 1) * 2;
            MMA16816(s[ng], fa, gb[q][rr],     gb[q][rr]);      // f . g_hi
            MMA16816(s[ng], fa, gb[q][rr + 1], gb[q][rr + 1]);  // f . g_lo
        }

        // exp + causal-ish mask (n_glob >= m_glob)
        const int off = n0 - m_base;
        if (off < 128) {
            #pragma unroll
            for (int ng = 0; ng < 8; ng++) {
                int d = off + ng * 8 + nbase - mloc;
                s[ng][0] = (d     >= 0) ? __expf(s[ng][0]) : 0.f;
                s[ng][1] = (d + 1 >= 0) ? __expf(s[ng][1]) : 0.f;
                s[ng][2] = (d - 8 >= 0) ? __expf(s[ng][2]) : 0.f;
                s[ng][3] = (d - 7 >= 0) ? __expf(s[ng][3]) : 0.f;
            }
        } else {
            #pragma unroll
            for (int ng = 0; ng < 8; ng++) {
                s[ng][0] = __expf(s[ng][0]);
                s[ng][1] = __expf(s[ng][1]);
                s[ng][2] = __expf(s[ng][2]);
                s[ng][3] = __expf(s[ng][3]);
            }
        }

        // pack P fragments (registers): 4 k16 A-frags
        unsigned pa[4][4];
        #pragma unroll
        for (int j = 0; j < 4; j++) {
            pa[j][0] = pk(s[2 * j][1],     s[2 * j][0]);
            pa[j][1] = pk(s[2 * j][3],     s[2 * j][2]);
            pa[j][2] = pk(s[2 * j + 1][1], s[2 * j + 1][0]);
            pa[j][3] = pk(s[2 * j + 1][3], s[2 * j + 1][2]);
        }

        // O += P @ V'
        #pragma unroll
        for (int j = 0; j < 4; j++) {
            const int kb = j * 16;
            unsigned vb[4][4];
            #pragma unroll
            for (int q2 = 0; q2 < 4; q2++) {
                unsigned addr = vtS + (((q2 * 16 + grow) * 72 + kb + gcol) << 1);
                LDSM4(vb[q2][0], vb[q2][1], vb[q2][2], vb[q2][3], addr);
            }
            #pragma unroll
            for (int cg = 0; cg < 8; cg++) {
                const int q2 = cg >> 1, rr = (cg & 1) * 2;
                MMA16816(accO[cg], pa[j], vb[q2][rr], vb[q2][rr + 1]);
            }
        }
    }

    // epilogue: atomic accumulate into g_O[b][c][m]
    const int m0g = m_base + wm16 + (lane >> 2);
    #pragma unroll
    for (int cg = 0; cg < 8; cg++) {
        int c = cg * 8 + nbase;
        atomicAdd(&g_O[((b * 64 + c    ) << 12) + m0g],     accO[cg][0]);
        atomicAdd(&g_O[((b * 64 + c + 1) << 12) + m0g],     accO[cg][1]);
        atomicAdd(&g_O[((b * 64 + c    ) << 12) + m0g + 8], accO[cg][2]);
        atomicAdd(&g_O[((b * 64 + c + 1) << 12) + m0g + 8], accO[cg][3]);
    }
}

// ---------------------------------------------------------------------------
__global__ __launch_bounds__(256) void kE(
    const float* __restrict__ x,
    const float* __restrict__ gamma,
    float* __restrict__ out)
{
    const float gm = gamma[0];
    int i = blockIdx.x * 256 + threadIdx.x;
    float4 o  = ((const float4*)g_O)[i];
    float4 xv = ((const float4*)x)[i];
    ((float4*)out)[i] = make_float4(gm * o.x + xv.x, gm * o.y + xv.y,
                                    gm * o.z + xv.z, gm * o.w + xv.w);
}

// ---------------------------------------------------------------------------
extern "C" void kernel_launch(void* const* d_in, const int* in_sizes, int n_in,
                              void* d_out, int out_size)
{
    const float* x     = (const float*)d_in[0];
    const float* Wf    = (const float*)d_in[1];
    const float* bf    = (const float*)d_in[2];
    const float* Wg    = (const float*)d_in[3];
    const float* bg    = (const float*)d_in[4];
    const float* Wh    = (const float*)d_in[5];
    const float* bh    = (const float*)d_in[6];
    const float* gamma = (const float*)d_in[7];
    float* out = (float*)d_out;

    kZ<<<1024, 256>>>();
    kZ2<<<16, 256>>>();
    kA<<<dim3(32, 4), 256>>>(x, Wf, bf, Wg, bg, Wh, bh);
    kB1<<<dim3(64, 4), 256>>>();
    kB2<<<64, 256>>>();
    kV<<<1024, 256>>>();
    kC<<<320, 256>>>();
    kE<<<1024, 256>>>(x, gamma, out);
}